// round 1
// baseline (speedup 1.0000x reference)
#include <cuda_runtime.h>

// Local Attention (Point-Transformer style), fused single kernel, fp32.
// B=8, M=4096, K=16 neighbors, C=D=64.
// Block = 16 m-points x 16 neighbors = 256 threads; thread owns one (m,n) row.

#define BB 8
#define MM 4096
#define NK 16
#define CC 64
#define DD 64
#define MT 16
#define THREADS 256
#define WSTRIDE 68   // floats per weight row in smem (conflict padding)
#define W4S 17       // float4s per weight row

// dynamic smem layout, in floats
#define OFF_WQ   0
#define OFF_WK   4352
#define OFF_WV   8704
#define OFF_WP2  13056
#define OFF_WA1  17408
#define OFF_WA2  21760
#define OFF_W2   26112
#define OFF_WP1  30464            // 64 x 4 (padded from 64x3)
#define OFF_B    30720            // 8 x 64 biases: bq,bk,bv,bp1,bp2,ba1,ba2,b2
#define OFF_Q    31232            // MT x 65
#define OFF_RES  32272            // MT x 65
#define OFF_VPE  33312            // MT*16 x 65
#define SMEM_FLOATS 49952
#define SMEM_BYTES (SMEM_FLOATS * 4)   // 199808 B

__device__ __forceinline__ float hw_max16(float v) {
    v = fmaxf(v, __shfl_xor_sync(0xffffffffu, v, 8));
    v = fmaxf(v, __shfl_xor_sync(0xffffffffu, v, 4));
    v = fmaxf(v, __shfl_xor_sync(0xffffffffu, v, 2));
    v = fmaxf(v, __shfl_xor_sync(0xffffffffu, v, 1));
    return v;
}

__global__ void __launch_bounds__(THREADS, 1)
la_kernel(const float* __restrict__ x,   const float* __restrict__ xyz,
          const float* __restrict__ Wq,  const float* __restrict__ bq,
          const float* __restrict__ Wk,  const float* __restrict__ bk,
          const float* __restrict__ Wv,  const float* __restrict__ bv,
          const float* __restrict__ Wp1, const float* __restrict__ bp1,
          const float* __restrict__ Wp2, const float* __restrict__ bp2,
          const float* __restrict__ Wa1, const float* __restrict__ ba1,
          const float* __restrict__ Wa2, const float* __restrict__ ba2,
          const float* __restrict__ W2,  const float* __restrict__ b2,
          float* __restrict__ out)
{
    extern __shared__ float sm[];
    const int tid = threadIdx.x;

    // ---- cooperative weight/bias staging into smem (row stride 68) ----
    {
        const float* gsrc[7] = {Wq, Wk, Wv, Wp2, Wa1, Wa2, W2};
        const int    soff[7] = {OFF_WQ, OFF_WK, OFF_WV, OFF_WP2, OFF_WA1, OFF_WA2, OFF_W2};
#pragma unroll
        for (int w = 0; w < 7; w++) {
            const float4* g4 = (const float4*)gsrc[w];
            float4* s4 = (float4*)(sm + soff[w]);
#pragma unroll
            for (int it = 0; it < 4; it++) {
                int idx = tid + it * THREADS;          // 0..1023 float4s
                int row = idx >> 4, c4 = idx & 15;
                s4[row * W4S + c4] = __ldg(g4 + idx);
            }
        }
        if (tid < 192) {                                // Wp1: 64x3 -> pad to x4
            sm[OFF_WP1 + (tid / 3) * 4 + (tid % 3)] = __ldg(Wp1 + tid);
        }
        const float* bsrc[8] = {bq, bk, bv, bp1, bp2, ba1, ba2, b2};
#pragma unroll
        for (int it = 0; it < 2; it++) {
            int idx = tid + it * THREADS;               // 0..511
            sm[OFF_B + idx] = __ldg(bsrc[idx >> 6] + (idx & 63));
        }
    }
    __syncthreads();

    const int bix = blockIdx.x;
    const int b   = bix >> 8;                 // M/MT = 256 tiles per batch
    const int m0  = (bix & 255) * MT;
    const int mi  = tid >> 4;
    const int n   = tid & 15;
    const int m   = m0 + mi;
    const int g   = tid;                      // mi*16 + n
    const size_t rowbase = ((size_t)(b * MM + m)) * NK;
    const float* xrow  = x   + (rowbase + n) * CC;
    const float* x0row = x   + rowbase * CC;
    const float* zrow  = xyz + (rowbase + n) * 3;
    const float* z0row = xyz + rowbase * 3;

    // ---- q (distributed across the 16 threads of each m): d = n + 16j ----
    {
        float qa[4];
#pragma unroll
        for (int j = 0; j < 4; j++) qa[j] = sm[OFF_B + 0 * 64 + n + 16 * j];
        const float4* x0p = (const float4*)x0row;
        const float4* wq4 = (const float4*)(sm + OFF_WQ);
#pragma unroll
        for (int c4 = 0; c4 < 16; c4++) {
            float4 xv = __ldg(x0p + c4);
#pragma unroll
            for (int j = 0; j < 4; j++) {
                float4 w = wq4[(n + 16 * j) * W4S + c4];
                qa[j] += xv.x * w.x + xv.y * w.y + xv.z * w.z + xv.w * w.w;
            }
        }
#pragma unroll
        for (int j = 0; j < 4; j++) sm[OFF_Q + mi * 65 + n + 16 * j] = qa[j];
    }

    // ---- pos-MLP hidden: hp = relu(rel @ Wp1^T + bp1), reg-resident ----
    float hp[64];
    {
        float r0 = __ldg(zrow + 0) - __ldg(z0row + 0);
        float r1 = __ldg(zrow + 1) - __ldg(z0row + 1);
        float r2 = __ldg(zrow + 2) - __ldg(z0row + 2);
#pragma unroll
        for (int d = 0; d < 64; d++) {
            const float* wp = sm + OFF_WP1 + d * 4;
            float v = sm[OFF_B + 3 * 64 + d];
            v = fmaf(r0, wp[0], v);
            v = fmaf(r1, wp[1], v);
            v = fmaf(r2, wp[2], v);
            hp[d] = fmaxf(v, 0.0f);
        }
    }

    // ---- x row to registers ----
    float xr[64];
    {
        const float4* xp = (const float4*)xrow;
#pragma unroll
        for (int c4 = 0; c4 < 16; c4++) {
            float4 v = __ldg(xp + c4);
            xr[4 * c4 + 0] = v.x; xr[4 * c4 + 1] = v.y;
            xr[4 * c4 + 2] = v.z; xr[4 * c4 + 3] = v.w;
        }
    }
    __syncwarp();   // sQ visible within warp

    // ---- per-d: pos_enc, k, v ;  h -> local, (v+pos) -> smem ----
    float hloc[64];   // dynamic-indexed writes -> local memory (256 B/thread)
    {
#pragma unroll 1
        for (int d = 0; d < 64; d++) {
            const float4* rp = (const float4*)(sm + OFF_WP2 + d * WSTRIDE);
            const float4* rk = (const float4*)(sm + OFF_WK  + d * WSTRIDE);
            const float4* rv = (const float4*)(sm + OFF_WV  + d * WSTRIDE);
            float px = 0.f, py = 0.f, pz = 0.f, pw = 0.f;
            float kx = 0.f, ky = 0.f, kz = 0.f, kw = 0.f;
            float vx = 0.f, vy = 0.f, vz = 0.f, vw = 0.f;
#pragma unroll
            for (int c4 = 0; c4 < 16; c4++) {
                float4 wp = rp[c4], wk = rk[c4], wv = rv[c4];
                float h0 = hp[4 * c4 + 0], h1 = hp[4 * c4 + 1];
                float h2 = hp[4 * c4 + 2], h3 = hp[4 * c4 + 3];
                float a0 = xr[4 * c4 + 0], a1v = xr[4 * c4 + 1];
                float a2 = xr[4 * c4 + 2], a3 = xr[4 * c4 + 3];
                px = fmaf(h0, wp.x, px); py = fmaf(h1, wp.y, py);
                pz = fmaf(h2, wp.z, pz); pw = fmaf(h3, wp.w, pw);
                kx = fmaf(a0, wk.x, kx); ky = fmaf(a1v, wk.y, ky);
                kz = fmaf(a2, wk.z, kz); kw = fmaf(a3, wk.w, kw);
                vx = fmaf(a0, wv.x, vx); vy = fmaf(a1v, wv.y, vy);
                vz = fmaf(a2, wv.z, vz); vw = fmaf(a3, wv.w, vw);
            }
            float pos = sm[OFF_B + 4 * 64 + d] + (px + py) + (pz + pw);
            float kk  = sm[OFF_B + 1 * 64 + d] + (kx + ky) + (kz + kw);
            float vv  = sm[OFF_B + 2 * 64 + d] + (vx + vy) + (vz + vw);
            hloc[d] = sm[OFF_Q + mi * 65 + d] - kk + pos;
            sm[OFF_VPE + g * 65 + d] = vv + pos;
        }
    }

    // ---- a1 = relu(h @ Wa1^T + ba1), a1 reg-resident (chunked full unroll) ----
    float a1[64];
#pragma unroll
    for (int d = 0; d < 64; d++) a1[d] = sm[OFF_B + 5 * 64 + d];
#pragma unroll
    for (int cb = 0; cb < 4; cb++) {
        float hc[16];
#pragma unroll
        for (int i = 0; i < 16; i++) hc[i] = hloc[cb * 16 + i];
#pragma unroll
        for (int d = 0; d < 64; d++) {
            const float4* r = (const float4*)(sm + OFF_WA1 + d * WSTRIDE + cb * 16);
            float4 w0 = r[0], w1 = r[1], w2 = r[2], w3 = r[3];
            float s0 = hc[0]  * w0.x + hc[1]  * w0.y + hc[2]  * w0.z + hc[3]  * w0.w;
            float s1 = hc[4]  * w1.x + hc[5]  * w1.y + hc[6]  * w1.z + hc[7]  * w1.w;
            float s2 = hc[8]  * w2.x + hc[9]  * w2.y + hc[10] * w2.z + hc[11] * w2.w;
            float s3 = hc[12] * w3.x + hc[13] * w3.y + hc[14] * w3.z + hc[15] * w3.w;
            a1[d] += (s0 + s1) + (s2 + s3);
        }
    }
#pragma unroll
    for (int d = 0; d < 64; d++) a1[d] = fmaxf(a1[d], 0.0f);

    // ---- logits + softmax over the 16 neighbors + weighted sum, per d ----
#pragma unroll 2
    for (int d = 0; d < 64; d++) {
        const float4* r = (const float4*)(sm + OFF_WA2 + d * WSTRIDE);
        float ax = 0.f, ay = 0.f, az = 0.f, aw = 0.f;
#pragma unroll
        for (int c4 = 0; c4 < 16; c4++) {
            float4 w = r[c4];
            ax = fmaf(a1[4 * c4 + 0], w.x, ax);
            ay = fmaf(a1[4 * c4 + 1], w.y, ay);
            az = fmaf(a1[4 * c4 + 2], w.z, az);
            aw = fmaf(a1[4 * c4 + 3], w.w, aw);
        }
        float lg = sm[OFF_B + 6 * 64 + d] + (ax + ay) + (az + aw);
        float mx = hw_max16(lg);
        float e  = __expf((lg - mx) * 0.125f);        // /sqrt(64)
        float vv = sm[OFF_VPE + g * 65 + d];
        float s  = e;
        float we = e * vv;
        s  += __shfl_xor_sync(0xffffffffu, s, 8);  we += __shfl_xor_sync(0xffffffffu, we, 8);
        s  += __shfl_xor_sync(0xffffffffu, s, 4);  we += __shfl_xor_sync(0xffffffffu, we, 4);
        s  += __shfl_xor_sync(0xffffffffu, s, 2);  we += __shfl_xor_sync(0xffffffffu, we, 2);
        s  += __shfl_xor_sync(0xffffffffu, s, 1);  we += __shfl_xor_sync(0xffffffffu, we, 1);
        if (n == 0) sm[OFF_RES + mi * 65 + d] = we / s;
    }
    __syncwarp();

    // ---- final: out = res @ W2^T + b2 + raw_feature ----
#pragma unroll
    for (int j = 0; j < 4; j++) {
        int c = n + 16 * j;
        const float4* r = (const float4*)(sm + OFF_W2 + c * WSTRIDE);
        const float* rs = sm + OFF_RES + mi * 65;
        float ax = 0.f, ay = 0.f, az = 0.f, aw = 0.f;
#pragma unroll
        for (int d4 = 0; d4 < 16; d4++) {
            float4 w = r[d4];
            ax = fmaf(rs[4 * d4 + 0], w.x, ax);
            ay = fmaf(rs[4 * d4 + 1], w.y, ay);
            az = fmaf(rs[4 * d4 + 2], w.z, az);
            aw = fmaf(rs[4 * d4 + 3], w.w, aw);
        }
        float o = sm[OFF_B + 7 * 64 + c] + (ax + ay) + (az + aw) + __ldg(x0row + c);
        out[((size_t)(b * MM + m)) * CC + c] = o;
    }
}

extern "C" void kernel_launch(void* const* d_in, const int* in_sizes, int n_in,
                              void* d_out, int out_size)
{
    const float* x   = (const float*)d_in[0];
    const float* xyz = (const float*)d_in[1];
    const float* Wq  = (const float*)d_in[2];
    const float* bq  = (const float*)d_in[3];
    const float* Wk  = (const float*)d_in[4];
    const float* bk  = (const float*)d_in[5];
    const float* Wv  = (const float*)d_in[6];
    const float* bv  = (const float*)d_in[7];
    const float* Wp1 = (const float*)d_in[8];
    const float* bp1 = (const float*)d_in[9];
    const float* Wp2 = (const float*)d_in[10];
    const float* bp2 = (const float*)d_in[11];
    const float* Wa1 = (const float*)d_in[12];
    const float* ba1 = (const float*)d_in[13];
    const float* Wa2 = (const float*)d_in[14];
    const float* ba2 = (const float*)d_in[15];
    const float* W2  = (const float*)d_in[16];
    const float* b2  = (const float*)d_in[17];

    cudaFuncSetAttribute(la_kernel, cudaFuncAttributeMaxDynamicSharedMemorySize, SMEM_BYTES);

    dim3 grid(BB * MM / MT);   // 2048 blocks
    dim3 block(THREADS);
    la_kernel<<<grid, block, SMEM_BYTES>>>(x, xyz, Wq, bq, Wk, bk, Wv, bv,
                                           Wp1, bp1, Wp2, bp2, Wa1, ba1,
                                           Wa2, ba2, W2, b2, (float*)d_out);
}

// round 7
// speedup vs baseline: 2.4970x; 2.4970x over previous
#include <cuda_runtime.h>
#include <cstdint>

// Fused local attention, warp-level tf32 mma.sync (baseline sm_103 PTX — no tcgen05).
// B=8, M=4096, K=16 neighbors, C=D=64. Tile = 128 rows (8 m-groups x 16 neighbors).
// 256 threads; warp w owns rows w*16..w*16+15 (= m-group w) end-to-end.

#define THREADS 256
#define NTILES  4096
#define GRID    152

// ---- smem layout in 32-bit words ----
#define OFF_CTRL  0          // word 4 = tile index
#define OFF_WF    256        // 6 weights in B-fragment order: [w][kt*512 + nt*64 + lane*2 + j]
#define OFF_OPX   24832      // X operand -> later H operand (128 x 68)
#define OFF_OPHP  33536      // HP operand -> later A1 operand (128 x 68)
#define OFF_OPX0  42240      // X0 operand (128 x 68)
#define OFF_W2    50944      // W2 fp32 row-major (64 x 68)
#define OFF_RES   55296      // res fp32 (8 x 68)
#define OFF_BIAS  55840      // 6 x 64: bh, bvpe, ba1, ba2, b2, bp1
#define OFF_WP1   56224      // Wp1 padded (64 x 4)
#define SMEM_WORDS 56480
#define SMEM_BYTES (SMEM_WORDS * 4)   // 225920

__device__ int g_ctr;
__global__ void zero_ctr() { g_ctr = 0; }

__device__ __forceinline__ uint32_t f2tf(float f) {
    uint32_t r; asm("cvt.rna.tf32.f32 %0, %1;" : "=r"(r) : "f"(f)); return r;
}

__device__ __forceinline__ void mma_tf(float c[4], const uint32_t a[4], uint32_t b0, uint32_t b1) {
    asm volatile(
        "mma.sync.aligned.m16n8k8.row.col.f32.tf32.tf32.f32 "
        "{%0,%1,%2,%3}, {%4,%5,%6,%7}, {%8,%9}, {%0,%1,%2,%3};"
        : "+f"(c[0]), "+f"(c[1]), "+f"(c[2]), "+f"(c[3])
        : "r"(a[0]), "r"(a[1]), "r"(a[2]), "r"(a[3]), "r"(b0), "r"(b1));
}

// A fragments for one m16 tile: base points at this warp's row block (row-major, stride 68).
// Bank-conflict-free: bank = (4*(lane>>2) + (lane&3)) is a bijection on 32 lanes.
__device__ __forceinline__ void load_af(uint32_t af[8][4], const uint32_t* base, int lr, int lc) {
#pragma unroll
    for (int kt = 0; kt < 8; kt++) {
        const uint32_t* p0 = base + lr * 68 + kt * 8 + lc;
        const uint32_t* p1 = p0 + 8 * 68;
        af[kt][0] = p0[0]; af[kt][2] = p0[4];
        af[kt][1] = p1[0]; af[kt][3] = p1[4];
    }
}

// 16x64x64 GEMM-accumulate for one warp: 64 mma + 64 broadcast LDS.64 of weight fragments.
__device__ __forceinline__ void gemm64(float c[8][4], const uint32_t af[8][4],
                                       const uint32_t* wf, int lane) {
#pragma unroll
    for (int nt = 0; nt < 8; nt++) {
#pragma unroll
        for (int kt = 0; kt < 8; kt++) {
            uint2 b = *(const uint2*)(wf + kt * 512 + nt * 64 + lane * 2);
            mma_tf(c[nt], af[kt], b.x, b.y);
        }
    }
}

__global__ void __launch_bounds__(THREADS, 1)
la_mma(const float* __restrict__ x,   const float* __restrict__ xyz,
       const float* __restrict__ Wq,  const float* __restrict__ bq,
       const float* __restrict__ Wk,  const float* __restrict__ bk,
       const float* __restrict__ Wv,  const float* __restrict__ bv,
       const float* __restrict__ Wp1, const float* __restrict__ bp1,
       const float* __restrict__ Wp2, const float* __restrict__ bp2,
       const float* __restrict__ Wa1, const float* __restrict__ ba1,
       const float* __restrict__ Wa2, const float* __restrict__ ba2,
       const float* __restrict__ W2,  const float* __restrict__ b2,
       float* __restrict__ out)
{
    extern __shared__ float smf[];
    uint32_t* smu = (uint32_t*)smf;
    const int tid  = threadIdx.x;
    const int wid  = tid >> 5;
    const int lane = tid & 31;
    const int lr   = lane >> 2;
    const int lc   = lane & 3;

    // ---------------- prologue: stage weights once per CTA ----------------
    {
        const float* gsrc[6] = {Wq, Wk, Wv, Wp2, Wa1, Wa2};
#pragma unroll 1
        for (int w = 0; w < 6; w++) {
            float sgn = (w == 1) ? -1.0f : 1.0f;   // Wk negated: h = q + x@(-Wk)^T + pos
#pragma unroll
            for (int i = 0; i < 16; i++) {
                int e = tid + i * 256;             // 0..4095, layout kt*512 + nt*64 + lane*2 + j
                int j = e & 1, ln = (e >> 1) & 31, nt = (e >> 6) & 7, kt = e >> 9;
                int n = nt * 8 + (ln >> 2);
                int k = kt * 8 + (ln & 3) + 4 * j;
                smu[OFF_WF + w * 4096 + e] = f2tf(sgn * __ldg(gsrc[w] + n * 64 + k));
            }
        }
#pragma unroll
        for (int i = 0; i < 16; i++) {             // W2 row-major stride 68
            int e = tid + i * 256;
            smf[OFF_W2 + (e >> 6) * 68 + (e & 63)] = __ldg(W2 + e);
        }
        if (tid < 64) {
            int d = tid;
            smf[OFF_BIAS + 0 * 64 + d] = __ldg(bq + d) - __ldg(bk + d) + __ldg(bp2 + d); // bh
            smf[OFF_BIAS + 1 * 64 + d] = __ldg(bv + d) + __ldg(bp2 + d);                 // bvpe
            smf[OFF_BIAS + 2 * 64 + d] = __ldg(ba1 + d);
            smf[OFF_BIAS + 3 * 64 + d] = __ldg(ba2 + d);
            smf[OFF_BIAS + 4 * 64 + d] = __ldg(b2 + d);
            smf[OFF_BIAS + 5 * 64 + d] = __ldg(bp1 + d);
            smf[OFF_WP1 + 4 * d + 0] = __ldg(Wp1 + 3 * d + 0);
            smf[OFF_WP1 + 4 * d + 1] = __ldg(Wp1 + 3 * d + 1);
            smf[OFF_WP1 + 4 * d + 2] = __ldg(Wp1 + 3 * d + 2);
            smf[OFF_WP1 + 4 * d + 3] = 0.0f;
        }
    }
    __syncthreads();

    const uint32_t* wfb = smu + OFF_WF;
    const int rb = wid * 16;                // this warp's row block = m-group wid

    for (;;) {
        if (tid == 0) *(volatile int*)(smu + 4) = atomicAdd(&g_ctr, 1);
        __syncthreads();
        const int t = *(volatile int*)(smu + 4);
        if (t >= NTILES) break;

        // ---------- stage X, X0, HP (thread = half-row: row tid>>1, 32 cols) ----------
        {
            const int r  = tid >> 1;
            const int ch = (tid & 1) * 32;
            const float4* gx  = (const float4*)(x + ((size_t)t * 128 + r) * 64 + ch);
            const float4* gx0 = (const float4*)(x + ((size_t)t * 128 + (r & ~15)) * 64 + ch);
#pragma unroll
            for (int i = 0; i < 8; i++) {
                float4 v = __ldg(gx + i);
                uint4 u; u.x = f2tf(v.x); u.y = f2tf(v.y); u.z = f2tf(v.z); u.w = f2tf(v.w);
                *(uint4*)(smu + OFF_OPX + r * 68 + ch + i * 4) = u;
                float4 v0 = __ldg(gx0 + i);
                uint4 u0; u0.x = f2tf(v0.x); u0.y = f2tf(v0.y); u0.z = f2tf(v0.z); u0.w = f2tf(v0.w);
                *(uint4*)(smu + OFF_OPX0 + r * 68 + ch + i * 4) = u0;
            }
            const float* gz  = xyz + ((size_t)t * 128 + r) * 3;
            const float* gz0 = xyz + ((size_t)t * 128 + (r & ~15)) * 3;
            float r0 = __ldg(gz + 0) - __ldg(gz0 + 0);
            float r1 = __ldg(gz + 1) - __ldg(gz0 + 1);
            float r2 = __ldg(gz + 2) - __ldg(gz0 + 2);
#pragma unroll
            for (int i = 0; i < 8; i++) {
                uint4 u;
                uint32_t* up = (uint32_t*)&u;
#pragma unroll
                for (int j = 0; j < 4; j++) {
                    int d = ch + i * 4 + j;
                    float4 wp = *(const float4*)(smf + OFF_WP1 + 4 * d);
                    float h = smf[OFF_BIAS + 5 * 64 + d];
                    h = fmaf(r0, wp.x, h); h = fmaf(r1, wp.y, h); h = fmaf(r2, wp.z, h);
                    up[j] = f2tf(fmaxf(h, 0.0f));
                }
                *(uint4*)(smu + OFF_OPHP + r * 68 + ch + i * 4) = u;
            }
        }
        __syncwarp();

        // ---------- fused GEMMs: lacc = x0@Wq + x@(-Wk) + hp@Wp2 ; vacc = x@Wv + hp@Wp2 ----------
        float lacc[8][4], vacc[8][4];
#pragma unroll
        for (int nt = 0; nt < 8; nt++)
#pragma unroll
            for (int j = 0; j < 4; j++) { lacc[nt][j] = 0.0f; vacc[nt][j] = 0.0f; }

        uint32_t af[8][4];
        load_af(af, smu + OFF_OPX0 + rb * 68, lr, lc);
        gemm64(lacc, af, wfb + 0 * 4096, lane);                  // Wq
        load_af(af, smu + OFF_OPX + rb * 68, lr, lc);
        gemm64(lacc, af, wfb + 1 * 4096, lane);                  // -Wk
        gemm64(vacc, af, wfb + 2 * 4096, lane);                  // Wv
        load_af(af, smu + OFF_OPHP + rb * 68, lr, lc);
        gemm64(lacc, af, wfb + 3 * 4096, lane);                  // Wp2 (h)
        gemm64(vacc, af, wfb + 3 * 4096, lane);                  // Wp2 (vpe)

        // ---------- h epilogue: +bh, tf32, store into OPX as next A operand ----------
#pragma unroll
        for (int nt = 0; nt < 8; nt++) {
            int c = nt * 8 + 2 * lc;
            float b0 = smf[OFF_BIAS + c], b1 = smf[OFF_BIAS + c + 1];
            uint2 u0; u0.x = f2tf(lacc[nt][0] + b0); u0.y = f2tf(lacc[nt][1] + b1);
            uint2 u1; u1.x = f2tf(lacc[nt][2] + b0); u1.y = f2tf(lacc[nt][3] + b1);
            *(uint2*)(smu + OFF_OPX + (rb + lr) * 68 + c)     = u0;
            *(uint2*)(smu + OFF_OPX + (rb + lr + 8) * 68 + c) = u1;
        }
        __syncwarp();

        // ---------- a1 = relu(h @ Wa1^T + ba1) ----------
        float aacc[8][4];
#pragma unroll
        for (int nt = 0; nt < 8; nt++)
#pragma unroll
            for (int j = 0; j < 4; j++) aacc[nt][j] = 0.0f;
        load_af(af, smu + OFF_OPX + rb * 68, lr, lc);
        gemm64(aacc, af, wfb + 4 * 4096, lane);                  // Wa1
#pragma unroll
        for (int nt = 0; nt < 8; nt++) {
            int c = nt * 8 + 2 * lc;
            float b0 = smf[OFF_BIAS + 2 * 64 + c], b1 = smf[OFF_BIAS + 2 * 64 + c + 1];
            uint2 u0; u0.x = f2tf(fmaxf(aacc[nt][0] + b0, 0.0f)); u0.y = f2tf(fmaxf(aacc[nt][1] + b1, 0.0f));
            uint2 u1; u1.x = f2tf(fmaxf(aacc[nt][2] + b0, 0.0f)); u1.y = f2tf(fmaxf(aacc[nt][3] + b1, 0.0f));
            *(uint2*)(smu + OFF_OPHP + (rb + lr) * 68 + c)     = u0;
            *(uint2*)(smu + OFF_OPHP + (rb + lr + 8) * 68 + c) = u1;
        }
        __syncwarp();

        // ---------- logits = a1 @ Wa2^T ----------
        float gacc[8][4];
#pragma unroll
        for (int nt = 0; nt < 8; nt++)
#pragma unroll
            for (int j = 0; j < 4; j++) gacc[nt][j] = 0.0f;
        load_af(af, smu + OFF_OPHP + rb * 68, lr, lc);
        gemm64(gacc, af, wfb + 5 * 4096, lane);                  // Wa2

        // ---------- softmax over 16 neighbors (in C-fragment domain) + weighted sum ----------
#pragma unroll
        for (int nt = 0; nt < 8; nt++) {
            int c = nt * 8 + 2 * lc;
#pragma unroll
            for (int jc = 0; jc < 2; jc++) {
                float ba = smf[OFF_BIAS + 3 * 64 + c + jc];
                float l0 = (gacc[nt][jc]     + ba) * 0.125f;     // row lr
                float l2 = (gacc[nt][jc + 2] + ba) * 0.125f;     // row lr+8
                float mx = fmaxf(l0, l2);
                mx = fmaxf(mx, __shfl_xor_sync(0xffffffffu, mx, 4));
                mx = fmaxf(mx, __shfl_xor_sync(0xffffffffu, mx, 8));
                mx = fmaxf(mx, __shfl_xor_sync(0xffffffffu, mx, 16));
                float e0 = __expf(l0 - mx), e2 = __expf(l2 - mx);
                float bv = smf[OFF_BIAS + 64 + c + jc];
                float v0 = vacc[nt][jc] + bv, v2 = vacc[nt][jc + 2] + bv;
                float s = e0 + e2;
                float w = e0 * v0 + e2 * v2;
                s += __shfl_xor_sync(0xffffffffu, s, 4);  w += __shfl_xor_sync(0xffffffffu, w, 4);
                s += __shfl_xor_sync(0xffffffffu, s, 8);  w += __shfl_xor_sync(0xffffffffu, w, 8);
                s += __shfl_xor_sync(0xffffffffu, s, 16); w += __shfl_xor_sync(0xffffffffu, w, 16);
                if (lr == 0) smf[OFF_RES + wid * 68 + c + jc] = w / s;
            }
        }
        __syncthreads();

        // ---------- final: out = res @ W2^T + b2 + raw_feature ----------
#pragma unroll
        for (int i = 0; i < 2; i++) {
            int o = tid + i * 256;                  // 0..511
            int m = o >> 6, c = o & 63;
            const float4* rr = (const float4*)(smf + OFF_RES + m * 68);
            const float4* wr = (const float4*)(smf + OFF_W2 + c * 68);
            float ax = 0.f, ay = 0.f, az = 0.f, aw = 0.f;
#pragma unroll
            for (int d4 = 0; d4 < 16; d4++) {
                float4 rv = rr[d4], wv = wr[d4];
                ax = fmaf(rv.x, wv.x, ax);
                ay = fmaf(rv.y, wv.y, ay);
                az = fmaf(rv.z, wv.z, az);
                aw = fmaf(rv.w, wv.w, aw);
            }
            float oo = smf[OFF_BIAS + 4 * 64 + c] + (ax + ay) + (az + aw)
                     + __ldg(x + ((size_t)t * 128 + m * 16) * 64 + c);
            out[((size_t)t * 8 + m) * 64 + c] = oo;
        }
        // top-of-loop __syncthreads() separates RES reads from next tile's writes
    }
}

extern "C" void kernel_launch(void* const* d_in, const int* in_sizes, int n_in,
                              void* d_out, int out_size)
{
    const float* x   = (const float*)d_in[0];
    const float* xyz = (const float*)d_in[1];
    const float* Wq  = (const float*)d_in[2];
    const float* bq  = (const float*)d_in[3];
    const float* Wk  = (const float*)d_in[4];
    const float* bk  = (const float*)d_in[5];
    const float* Wv  = (const float*)d_in[6];
    const float* bv  = (const float*)d_in[7];
    const float* Wp1 = (const float*)d_in[8];
    const float* bp1 = (const float*)d_in[9];
    const float* Wp2 = (const float*)d_in[10];
    const float* bp2 = (const float*)d_in[11];
    const float* Wa1 = (const float*)d_in[12];
    const float* ba1 = (const float*)d_in[13];
    const float* Wa2 = (const float*)d_in[14];
    const float* ba2 = (const float*)d_in[15];
    const float* W2  = (const float*)d_in[16];
    const float* b2  = (const float*)d_in[17];

    cudaFuncSetAttribute(la_mma, cudaFuncAttributeMaxDynamicSharedMemorySize, SMEM_BYTES);

    zero_ctr<<<1, 1>>>();
    la_mma<<<GRID, THREADS, SMEM_BYTES>>>(x, xyz, Wq, bq, Wk, bk, Wv, bv,
                                          Wp1, bp1, Wp2, bp2, Wa1, ba1,
                                          Wa2, ba2, W2, b2, (float*)d_out);
}

// round 8
// speedup vs baseline: 3.9254x; 1.5720x over previous
#include <cuda_runtime.h>
#include <cstdint>

// Fused local attention, warp-level tf32 mma.sync. B=8,M=4096,K=16,C=D=64.
// 512 threads; tile = 256 rows (16 m-groups x 16 neighbors); warp w owns m-group w.
// warp0 additionally computes q (16 distinct rows) via one gemm64;
// warp1 additionally runs the previous tile's final output GEMM (overlapped).

#define THREADS 512
#define NTILES  2048      // 524288 rows / 256
#define GRID    152

// ---- smem word offsets ----
#define OFF_WF   8                       // 7 * 4096 weight B-fragments (Wq,-Wk,Wv,Wp2,Wa1,Wa2,W2)
#define OFF_OP   (OFF_WF + 7*4096)       // 28680 : 256 x 68, X -> H -> A1 (tf32 bits)
#define OFF_Q    (OFF_OP + 256*68)       // 46088 : 16 x 68 fp32
#define OFF_RES  (OFF_Q + 16*68)         // 47176 : 16 x 68 (tf32 bits)
#define OFF_BIAS (OFF_RES + 16*68)       // 48264 : 6 x 64 (bh,bvpe,ba1,ba2,b2,bq)
#define OFF_WP1  (OFF_BIAS + 6*64)       // 48648 : 64 x 4 (w0,w1,w2,bp1)
#define SMEM_WORDS (OFF_WP1 + 256)       // 48904
#define SMEM_BYTES (SMEM_WORDS * 4)      // 195616

__device__ __forceinline__ uint32_t f2tf(float f) {
    uint32_t r; asm("cvt.rna.tf32.f32 %0, %1;" : "=r"(r) : "f"(f)); return r;
}

__device__ __forceinline__ void mma_tf(float c[4], const uint32_t a[4], uint32_t b0, uint32_t b1) {
    asm volatile(
        "mma.sync.aligned.m16n8k8.row.col.f32.tf32.tf32.f32 "
        "{%0,%1,%2,%3}, {%4,%5,%6,%7}, {%8,%9}, {%0,%1,%2,%3};"
        : "+f"(c[0]), "+f"(c[1]), "+f"(c[2]), "+f"(c[3])
        : "r"(a[0]), "r"(a[1]), "r"(a[2]), "r"(a[3]), "r"(b0), "r"(b1));
}

// A fragments from smem (row-major, stride 68; bank = 4*lr+lc is bijective -> conflict-free)
__device__ __forceinline__ void load_af(uint32_t af[8][4], const uint32_t* base, int lr, int lc) {
#pragma unroll
    for (int kt = 0; kt < 8; kt++) {
        const uint32_t* p0 = base + lr * 68 + kt * 8 + lc;
        const uint32_t* p1 = p0 + 8 * 68;
        af[kt][0] = p0[0]; af[kt][2] = p0[4];
        af[kt][1] = p1[0]; af[kt][3] = p1[4];
    }
}

__device__ __forceinline__ void gemm64(float c[8][4], const uint32_t af[8][4],
                                       const uint32_t* wf, int lane) {
#pragma unroll
    for (int nt = 0; nt < 8; nt++)
#pragma unroll
        for (int kt = 0; kt < 8; kt++) {
            uint2 b = *(const uint2*)(wf + kt * 512 + nt * 64 + lane * 2);
            mma_tf(c[nt], af[kt], b.x, b.y);
        }
}

// two GEMMs sharing the A fragments, distinct B (Wk -> cl, Wv -> cv)
__device__ __forceinline__ void gemm64_dual(float cl[8][4], float cv[8][4], const uint32_t af[8][4],
                                            const uint32_t* w1, const uint32_t* w2, int lane) {
#pragma unroll
    for (int nt = 0; nt < 8; nt++)
#pragma unroll
        for (int kt = 0; kt < 8; kt++) {
            uint2 b1 = *(const uint2*)(w1 + kt * 512 + nt * 64 + lane * 2);
            uint2 b2 = *(const uint2*)(w2 + kt * 512 + nt * 64 + lane * 2);
            mma_tf(cl[nt], af[kt], b1.x, b1.y);
            mma_tf(cv[nt], af[kt], b2.x, b2.y);
        }
}

// two GEMMs sharing BOTH A fragments and B (Wp2 into h and vpe accumulators)
__device__ __forceinline__ void gemm64_shared(float cl[8][4], float cv[8][4], const uint32_t af[8][4],
                                              const uint32_t* wf, int lane) {
#pragma unroll
    for (int nt = 0; nt < 8; nt++)
#pragma unroll
        for (int kt = 0; kt < 8; kt++) {
            uint2 b = *(const uint2*)(wf + kt * 512 + nt * 64 + lane * 2);
            mma_tf(cl[nt], af[kt], b.x, b.y);
            mma_tf(cv[nt], af[kt], b.x, b.y);
        }
}

__global__ void __launch_bounds__(THREADS, 1)
la_mma(const float* __restrict__ x,   const float* __restrict__ xyz,
       const float* __restrict__ Wq,  const float* __restrict__ bq,
       const float* __restrict__ Wk,  const float* __restrict__ bk,
       const float* __restrict__ Wv,  const float* __restrict__ bv,
       const float* __restrict__ Wp1, const float* __restrict__ bp1,
       const float* __restrict__ Wp2, const float* __restrict__ bp2,
       const float* __restrict__ Wa1, const float* __restrict__ ba1,
       const float* __restrict__ Wa2, const float* __restrict__ ba2,
       const float* __restrict__ W2,  const float* __restrict__ b2,
       float* __restrict__ out)
{
    extern __shared__ float smf[];
    uint32_t* smu = (uint32_t*)smf;
    const int tid  = threadIdx.x;
    const int wid  = tid >> 5;
    const int lane = tid & 31;
    const int lr   = lane >> 2;
    const int lc   = lane & 3;

    // ---------------- prologue: stage weight B-fragments once per CTA ----------------
    {
        const float* gsrc[7] = {Wq, Wk, Wv, Wp2, Wa1, Wa2, W2};
#pragma unroll 1
        for (int w = 0; w < 7; w++) {
            float sgn = (w == 1) ? -1.0f : 1.0f;   // Wk negated: h = q + x@(-Wk)^T + pos
#pragma unroll
            for (int i = 0; i < 8; i++) {
                int e = tid + i * 512;             // layout kt*512 + nt*64 + lane*2 + j
                int j = e & 1, ln = (e >> 1) & 31, nt = (e >> 6) & 7, kt = e >> 9;
                int n = nt * 8 + (ln >> 2);
                int k = kt * 8 + (ln & 3) + 4 * j;
                smu[OFF_WF + w * 4096 + e] = f2tf(sgn * __ldg(gsrc[w] + n * 64 + k));
            }
        }
        if (tid < 64) {
            int d = tid;
            smf[OFF_BIAS + 0 * 64 + d] = __ldg(bp2 + d) - __ldg(bk + d);          // bh
            smf[OFF_BIAS + 1 * 64 + d] = __ldg(bv + d) + __ldg(bp2 + d);          // bvpe
            smf[OFF_BIAS + 2 * 64 + d] = __ldg(ba1 + d);
            smf[OFF_BIAS + 3 * 64 + d] = __ldg(ba2 + d);
            smf[OFF_BIAS + 4 * 64 + d] = __ldg(b2 + d);
            smf[OFF_BIAS + 5 * 64 + d] = __ldg(bq + d);
            smf[OFF_WP1 + 4 * d + 0] = __ldg(Wp1 + 3 * d + 0);
            smf[OFF_WP1 + 4 * d + 1] = __ldg(Wp1 + 3 * d + 1);
            smf[OFF_WP1 + 4 * d + 2] = __ldg(Wp1 + 3 * d + 2);
            smf[OFF_WP1 + 4 * d + 3] = __ldg(bp1 + d);
        }
    }

    const uint32_t* wfb = smu + OFF_WF;
    const int rb = wid * 16;                  // this warp's rows = m-group wid
    int prev = -1;

    for (int t = blockIdx.x; ; t += GRID) {
        __syncthreads();   // prev softmax res-writes  <->  warp1 final res-reads; OP/Q reuse

        // ---- warp1: flush previous tile's final output GEMM (overlapped) ----
        if (wid == 1 && prev >= 0) {
            uint32_t af[8][4];
            load_af(af, smu + OFF_RES, lr, lc);
            float fa[8][4];
#pragma unroll
            for (int nt = 0; nt < 8; nt++)
#pragma unroll
                for (int j = 0; j < 4; j++) fa[nt][j] = 0.0f;
            gemm64(fa, af, wfb + 6 * 4096, lane);         // W2
            const size_t Rp = (size_t)prev * 256;
#pragma unroll
            for (int nt = 0; nt < 8; nt++) {
                int c = nt * 8 + 2 * lc;
                float2 bb = *(const float2*)(smf + OFF_BIAS + 4 * 64 + c);
                float2 r0 = __ldg((const float2*)(x + (Rp + (size_t)lr * 16) * 64 + c));
                float2 r1 = __ldg((const float2*)(x + (Rp + (size_t)(lr + 8) * 16) * 64 + c));
                float2 o0 = {fa[nt][0] + bb.x + r0.x, fa[nt][1] + bb.y + r0.y};
                float2 o1 = {fa[nt][2] + bb.x + r1.x, fa[nt][3] + bb.y + r1.y};
                *(float2*)(out + ((size_t)prev * 16 + lr) * 64 + c)     = o0;
                *(float2*)(out + ((size_t)prev * 16 + lr + 8) * 64 + c) = o1;
            }
        }
        if (t >= NTILES) break;
        const size_t R = (size_t)t * 256;

        // ---- warp0: q = x0 @ Wq^T + bq for the 16 distinct m-rows (overlapped) ----
        if (wid == 0) {
            uint32_t af[8][4];
#pragma unroll
            for (int kt = 0; kt < 8; kt++) {
                int c0 = kt * 8 + lc;
                const float* p0 = x + (R + (size_t)lr * 16) * 64 + c0;
                const float* p1 = x + (R + (size_t)(lr + 8) * 16) * 64 + c0;
                af[kt][0] = f2tf(__ldg(p0));     af[kt][2] = f2tf(__ldg(p0 + 4));
                af[kt][1] = f2tf(__ldg(p1));     af[kt][3] = f2tf(__ldg(p1 + 4));
            }
            float qa[8][4];
#pragma unroll
            for (int nt = 0; nt < 8; nt++)
#pragma unroll
                for (int j = 0; j < 4; j++) qa[nt][j] = 0.0f;
            gemm64(qa, af, wfb + 0 * 4096, lane);         // Wq
#pragma unroll
            for (int nt = 0; nt < 8; nt++) {
                int c = nt * 8 + 2 * lc;
                float2 bb = *(const float2*)(smf + OFF_BIAS + 5 * 64 + c);
                *(float2*)(smf + OFF_Q + lr * 68 + c)       = make_float2(qa[nt][0] + bb.x, qa[nt][1] + bb.y);
                *(float2*)(smf + OFF_Q + (lr + 8) * 68 + c) = make_float2(qa[nt][2] + bb.x, qa[nt][3] + bb.y);
            }
        }

        // ---- stage X (own rows) coalesced into OP as tf32 ----
        {
            const int r  = tid >> 1;
            const int ch = (tid & 1) * 32;
            const float4* gx = (const float4*)(x + (R + r) * 64 + ch);
            uint32_t* dst = smu + OFF_OP + r * 68 + ch;
#pragma unroll
            for (int i = 0; i < 8; i++) {
                float4 v = __ldg(gx + i);
                uint4 u; u.x = f2tf(v.x); u.y = f2tf(v.y); u.z = f2tf(v.z); u.w = f2tf(v.w);
                *(uint4*)(dst + i * 4) = u;
            }
        }
        __syncwarp();

        // ---- fused stage-1 GEMMs ----
        float lacc[8][4], vacc[8][4];
#pragma unroll
        for (int nt = 0; nt < 8; nt++)
#pragma unroll
            for (int j = 0; j < 4; j++) { lacc[nt][j] = 0.0f; vacc[nt][j] = 0.0f; }
        {
            uint32_t xaf[8][4];
            load_af(xaf, smu + OFF_OP + rb * 68, lr, lc);
            gemm64_dual(lacc, vacc, xaf, wfb + 1 * 4096, wfb + 2 * 4096, lane);   // -Wk, Wv
        }
        {
            // HP (pos-MLP hidden) directly into A-fragment registers
            const float* zb = xyz + (R + (size_t)wid * 16) * 3;
            float bx = __ldg(zb + 0), by = __ldg(zb + 1), bz = __ldg(zb + 2);
            float r00 = __ldg(zb + lr * 3 + 0) - bx;
            float r01 = __ldg(zb + lr * 3 + 1) - by;
            float r02 = __ldg(zb + lr * 3 + 2) - bz;
            float r10 = __ldg(zb + (lr + 8) * 3 + 0) - bx;
            float r11 = __ldg(zb + (lr + 8) * 3 + 1) - by;
            float r12 = __ldg(zb + (lr + 8) * 3 + 2) - bz;
            uint32_t hpaf[8][4];
#pragma unroll
            for (int kt = 0; kt < 8; kt++)
#pragma unroll
                for (int s = 0; s < 2; s++) {
                    int d = kt * 8 + lc + 4 * s;
                    float4 w = *(const float4*)(smf + OFF_WP1 + 4 * d);
                    float h0 = w.w; h0 = fmaf(r00, w.x, h0); h0 = fmaf(r01, w.y, h0); h0 = fmaf(r02, w.z, h0);
                    float h1 = w.w; h1 = fmaf(r10, w.x, h1); h1 = fmaf(r11, w.y, h1); h1 = fmaf(r12, w.z, h1);
                    hpaf[kt][2 * s + 0] = f2tf(fmaxf(h0, 0.0f));
                    hpaf[kt][2 * s + 1] = f2tf(fmaxf(h1, 0.0f));
                }
            gemm64_shared(lacc, vacc, hpaf, wfb + 3 * 4096, lane);                // Wp2 -> both
        }
        __syncthreads();   // q ready for everyone

        // ---- h epilogue: h = lacc + bh + q[m] -> tf32 -> OP (own rows, in place) ----
#pragma unroll
        for (int nt = 0; nt < 8; nt++) {
            int c = nt * 8 + 2 * lc;
            float2 qv = *(const float2*)(smf + OFF_Q + wid * 68 + c);
            float2 bh = *(const float2*)(smf + OFF_BIAS + c);
            uint2 u0, u1;
            u0.x = f2tf(lacc[nt][0] + bh.x + qv.x);
            u0.y = f2tf(lacc[nt][1] + bh.y + qv.y);
            u1.x = f2tf(lacc[nt][2] + bh.x + qv.x);
            u1.y = f2tf(lacc[nt][3] + bh.y + qv.y);
            *(uint2*)(smu + OFF_OP + (rb + lr) * 68 + c)     = u0;
            *(uint2*)(smu + OFF_OP + (rb + lr + 8) * 68 + c) = u1;
        }
        __syncwarp();

        // ---- a1 = relu(h @ Wa1^T + ba1) -> OP in place ----
        float aacc[8][4];
#pragma unroll
        for (int nt = 0; nt < 8; nt++)
#pragma unroll
            for (int j = 0; j < 4; j++) aacc[nt][j] = 0.0f;
        {
            uint32_t af[8][4];
            load_af(af, smu + OFF_OP + rb * 68, lr, lc);
            gemm64(aacc, af, wfb + 4 * 4096, lane);                               // Wa1
        }
#pragma unroll
        for (int nt = 0; nt < 8; nt++) {
            int c = nt * 8 + 2 * lc;
            float2 bb = *(const float2*)(smf + OFF_BIAS + 2 * 64 + c);
            uint2 u0, u1;
            u0.x = f2tf(fmaxf(aacc[nt][0] + bb.x, 0.0f));
            u0.y = f2tf(fmaxf(aacc[nt][1] + bb.y, 0.0f));
            u1.x = f2tf(fmaxf(aacc[nt][2] + bb.x, 0.0f));
            u1.y = f2tf(fmaxf(aacc[nt][3] + bb.y, 0.0f));
            *(uint2*)(smu + OFF_OP + (rb + lr) * 68 + c)     = u0;
            *(uint2*)(smu + OFF_OP + (rb + lr + 8) * 68 + c) = u1;
        }
        __syncwarp();

        // ---- logits = a1 @ Wa2^T ----
        float gacc[8][4];
#pragma unroll
        for (int nt = 0; nt < 8; nt++)
#pragma unroll
            for (int j = 0; j < 4; j++) gacc[nt][j] = 0.0f;
        {
            uint32_t af[8][4];
            load_af(af, smu + OFF_OP + rb * 68, lr, lc);
            gemm64(gacc, af, wfb + 5 * 4096, lane);                               // Wa2
        }

        // ---- softmax over 16 neighbors + weighted sum -> res (tf32) ----
#pragma unroll
        for (int nt = 0; nt < 8; nt++) {
            int c = nt * 8 + 2 * lc;
            float2 ba = *(const float2*)(smf + OFF_BIAS + 3 * 64 + c);
            float2 bv = *(const float2*)(smf + OFF_BIAS + 1 * 64 + c);
            float rr[2];
#pragma unroll
            for (int jc = 0; jc < 2; jc++) {
                float bav = jc ? ba.y : ba.x;
                float bvv = jc ? bv.y : bv.x;
                float l0 = (gacc[nt][jc]     + bav) * 0.125f;   // n = lr
                float l2 = (gacc[nt][jc + 2] + bav) * 0.125f;   // n = lr+8
                float mx = fmaxf(l0, l2);
                mx = fmaxf(mx, __shfl_xor_sync(0xffffffffu, mx, 4));
                mx = fmaxf(mx, __shfl_xor_sync(0xffffffffu, mx, 8));
                mx = fmaxf(mx, __shfl_xor_sync(0xffffffffu, mx, 16));
                float e0 = __expf(l0 - mx), e2 = __expf(l2 - mx);
                float v0 = vacc[nt][jc] + bvv, v2 = vacc[nt][jc + 2] + bvv;
                float s = e0 + e2;
                float w = e0 * v0 + e2 * v2;
                s += __shfl_xor_sync(0xffffffffu, s, 4);  w += __shfl_xor_sync(0xffffffffu, w, 4);
                s += __shfl_xor_sync(0xffffffffu, s, 8);  w += __shfl_xor_sync(0xffffffffu, w, 8);
                s += __shfl_xor_sync(0xffffffffu, s, 16); w += __shfl_xor_sync(0xffffffffu, w, 16);
                rr[jc] = w / s;
            }
            if (lr == 0) {
                uint2 u; u.x = f2tf(rr[0]); u.y = f2tf(rr[1]);
                *(uint2*)(smu + OFF_RES + wid * 68 + c) = u;
            }
        }
        prev = t;
    }
}

extern "C" void kernel_launch(void* const* d_in, const int* in_sizes, int n_in,
                              void* d_out, int out_size)
{
    const float* x   = (const float*)d_in[0];
    const float* xyz = (const float*)d_in[1];
    const float* Wq  = (const float*)d_in[2];
    const float* bq  = (const float*)d_in[3];
    const float* Wk  = (const float*)d_in[4];
    const float* bk  = (const float*)d_in[5];
    const float* Wv  = (const float*)d_in[6];
    const float* bv  = (const float*)d_in[7];
    const float* Wp1 = (const float*)d_in[8];
    const float* bp1 = (const float*)d_in[9];
    const float* Wp2 = (const float*)d_in[10];
    const float* bp2 = (const float*)d_in[11];
    const float* Wa1 = (const float*)d_in[12];
    const float* ba1 = (const float*)d_in[13];
    const float* Wa2 = (const float*)d_in[14];
    const float* ba2 = (const float*)d_in[15];
    const float* W2  = (const float*)d_in[16];
    const float* b2  = (const float*)d_in[17];

    cudaFuncSetAttribute(la_mma, cudaFuncAttributeMaxDynamicSharedMemorySize, SMEM_BYTES);

    la_mma<<<GRID, THREADS, SMEM_BYTES>>>(x, xyz, Wq, bq, Wk, bk, Wv, bv,
                                          Wp1, bp1, Wp2, bp2, Wa1, ba1,
                                          Wa2, ba2, W2, b2, (float*)d_out);
}

// round 10
// speedup vs baseline: 5.6204x; 1.4318x over previous
#include <cuda_runtime.h>
#include <cuda_bf16.h>
#include <cstdint>

// Fused local attention, warp-level bf16 mma.sync (m16n8k16, fp32 accum).
// B=8, M=4096, K=16 neighbors, C=D=64. Tile = 128 rows (8 m-groups x 16 neighbors).
// 256 threads/CTA, 2 CTAs/SM (304 CTAs). Warp w owns m-group w.
// warp0 also computes q (8 distinct rows); warp1 flushes previous tile's output GEMM.

#define THREADS 256
#define NTILES  4096        // 524288 rows / 128
#define GRID    304
#define TOTROWS 524288

// ---- smem word offsets ----
#define OFF_WF   8                        // 7 * 2048 : bf16 B-fragments [kt][np][lane][4]
#define OFF_OP   (OFF_WF + 7*2048)        // 14344 : 128 rows x 36 uints (bf16x2), X->H->A1
#define OFF_Q    (OFF_OP + 128*36)        // 18952 : 8 x 68 fp32
#define OFF_RES  (OFF_Q + 8*68)           // 19496 : 16 x 36 uints (bf16x2; rows 8..15 unused)
#define OFF_BIAS (OFF_RES + 16*36)        // 20072 : 6 x 64 fp32 (bh,bvpe,ba1,ba2,b2,bq)
#define OFF_WP1  (OFF_BIAS + 6*64)        // 20456 : 64 x 4 fp32 (w0,w1,w2,bp1)
#define SMEM_WORDS (OFF_WP1 + 256)        // 20712
#define SMEM_BYTES (SMEM_WORDS * 4)       // 82848

__device__ __forceinline__ uint32_t pk(float lo, float hi) {
    __nv_bfloat162 h = __floats2bfloat162_rn(lo, hi);   // x = lo (low half)
    return *(uint32_t*)&h;
}

__device__ __forceinline__ void mma_bf(float c[4], const uint32_t a[4], uint32_t b0, uint32_t b1) {
    asm volatile(
        "mma.sync.aligned.m16n8k16.row.col.f32.bf16.bf16.f32 "
        "{%0,%1,%2,%3}, {%4,%5,%6,%7}, {%8,%9}, {%0,%1,%2,%3};"
        : "+f"(c[0]), "+f"(c[1]), "+f"(c[2]), "+f"(c[3])
        : "r"(a[0]), "r"(a[1]), "r"(a[2]), "r"(a[3]), "r"(b0), "r"(b1));
}

// A fragments from smem (uint rows of 32 data + 4 pad = stride 36; bank = 4*lr+lc bijective)
__device__ __forceinline__ void load_af(uint32_t af[4][4], const uint32_t* base, int lr, int lc) {
#pragma unroll
    for (int kt = 0; kt < 4; kt++) {
        const uint32_t* p0 = base + lr * 36 + kt * 8 + lc;
        const uint32_t* p1 = p0 + 8 * 36;
        af[kt][0] = p0[0]; af[kt][2] = p0[4];
        af[kt][1] = p1[0]; af[kt][3] = p1[4];
    }
}

// 16x64x64 GEMM: B-fragments packed [kt][np][lane][4]; one LDS.128 feeds two mmas.
__device__ __forceinline__ void gemm64(float c[8][4], const uint32_t af[4][4],
                                       const uint32_t* wf, int lane) {
#pragma unroll
    for (int kt = 0; kt < 4; kt++)
#pragma unroll
        for (int np = 0; np < 4; np++) {
            uint4 b = *(const uint4*)(wf + ((kt * 4 + np) * 32 + lane) * 4);
            mma_bf(c[2 * np],     af[kt], b.x, b.y);
            mma_bf(c[2 * np + 1], af[kt], b.z, b.w);
        }
}

__device__ __forceinline__ void gemm64_dual(float cl[8][4], float cv[8][4], const uint32_t af[4][4],
                                            const uint32_t* w1, const uint32_t* w2, int lane) {
#pragma unroll
    for (int kt = 0; kt < 4; kt++)
#pragma unroll
        for (int np = 0; np < 4; np++) {
            uint4 b1 = *(const uint4*)(w1 + ((kt * 4 + np) * 32 + lane) * 4);
            uint4 b2 = *(const uint4*)(w2 + ((kt * 4 + np) * 32 + lane) * 4);
            mma_bf(cl[2 * np],     af[kt], b1.x, b1.y);
            mma_bf(cl[2 * np + 1], af[kt], b1.z, b1.w);
            mma_bf(cv[2 * np],     af[kt], b2.x, b2.y);
            mma_bf(cv[2 * np + 1], af[kt], b2.z, b2.w);
        }
}

__device__ __forceinline__ void gemm64_shared(float cl[8][4], float cv[8][4], const uint32_t af[4][4],
                                              const uint32_t* wf, int lane) {
#pragma unroll
    for (int kt = 0; kt < 4; kt++)
#pragma unroll
        for (int np = 0; np < 4; np++) {
            uint4 b = *(const uint4*)(wf + ((kt * 4 + np) * 32 + lane) * 4);
            mma_bf(cl[2 * np],     af[kt], b.x, b.y);
            mma_bf(cl[2 * np + 1], af[kt], b.z, b.w);
            mma_bf(cv[2 * np],     af[kt], b.x, b.y);
            mba: ;
            mma_bf(cv[2 * np + 1], af[kt], b.z, b.w);
        }
}

__global__ void __launch_bounds__(THREADS, 2)
la_mma(const float* __restrict__ x,   const float* __restrict__ xyz,
       const float* __restrict__ Wq,  const float* __restrict__ bq,
       const float* __restrict__ Wk,  const float* __restrict__ bk,
       const float* __restrict__ Wv,  const float* __restrict__ bv,
       const float* __restrict__ Wp1, const float* __restrict__ bp1,
       const float* __restrict__ Wp2, const float* __restrict__ bp2,
       const float* __restrict__ Wa1, const float* __restrict__ ba1,
       const float* __restrict__ Wa2, const float* __restrict__ ba2,
       const float* __restrict__ W2,  const float* __restrict__ b2,
       float* __restrict__ out)
{
    extern __shared__ float smf[];
    uint32_t* smu = (uint32_t*)smf;
    const int tid  = threadIdx.x;
    const int wid  = tid >> 5;
    const int lane = tid & 31;
    const int lr   = lane >> 2;
    const int lc   = lane & 3;

    // ---------------- prologue: stage weight B-fragments (bf16) once per CTA ----------------
    {
        const float* gsrc[7] = {Wq, Wk, Wv, Wp2, Wa1, Wa2, W2};
#pragma unroll 1
        for (int w = 0; w < 7; w++) {
            float sgn = (w == 1) ? -1.0f : 1.0f;   // Wk negated: h = q + x@(-Wk)^T + pos
#pragma unroll
            for (int i = 0; i < 8; i++) {
                int e  = tid + i * 256;            // 0..2047 = ((kt*4+np)*32 + lane)*4 + jj
                int jj = e & 3, ln = (e >> 2) & 31, np = (e >> 7) & 3, kt = (e >> 9) & 3;
                int nt = 2 * np + (jj >> 1), j = jj & 1;
                int n  = nt * 8 + (ln >> 2);
                int k0 = kt * 16 + 2 * (ln & 3) + 8 * j;
                float2 wv = __ldg((const float2*)(gsrc[w] + n * 64 + k0));
                smu[OFF_WF + w * 2048 + e] = pk(sgn * wv.x, sgn * wv.y);
            }
        }
        if (tid < 64) {
            int d = tid;
            smf[OFF_BIAS + 0 * 64 + d] = __ldg(bp2 + d) - __ldg(bk + d);          // bh
            smf[OFF_BIAS + 1 * 64 + d] = __ldg(bv + d) + __ldg(bp2 + d);          // bvpe
            smf[OFF_BIAS + 2 * 64 + d] = __ldg(ba1 + d);
            smf[OFF_BIAS + 3 * 64 + d] = __ldg(ba2 + d);
            smf[OFF_BIAS + 4 * 64 + d] = __ldg(b2 + d);
            smf[OFF_BIAS + 5 * 64 + d] = __ldg(bq + d);
            smf[OFF_WP1 + 4 * d + 0] = __ldg(Wp1 + 3 * d + 0);
            smf[OFF_WP1 + 4 * d + 1] = __ldg(Wp1 + 3 * d + 1);
            smf[OFF_WP1 + 4 * d + 2] = __ldg(Wp1 + 3 * d + 2);
            smf[OFF_WP1 + 4 * d + 3] = __ldg(bp1 + d);
        }
    }

    const uint32_t* wfb = smu + OFF_WF;
    const int rb = wid * 16;                  // this warp's rows = m-group wid
    int prev = -1;

    for (int t = blockIdx.x; ; t += GRID) {
        __syncthreads();   // prev res-writes <-> warp1 res-reads; OP/Q reuse

        // ---- warp1: flush previous tile's final output GEMM (overlapped) ----
        if (wid == 1 && prev >= 0) {
            uint32_t af[4][4];
            load_af(af, smu + OFF_RES, lr, lc);
            float fa[8][4];
#pragma unroll
            for (int nt = 0; nt < 8; nt++)
#pragma unroll
                for (int j = 0; j < 4; j++) fa[nt][j] = 0.0f;
            gemm64(fa, af, wfb + 6 * 2048, lane);                 // W2
            const size_t Rp = (size_t)prev * 128;
#pragma unroll
            for (int nt = 0; nt < 8; nt++) {
                int c = nt * 8 + 2 * lc;
                float2 bb = *(const float2*)(smf + OFF_BIAS + 4 * 64 + c);
                float2 r0 = __ldg((const float2*)(x + (Rp + (size_t)lr * 16) * 64 + c));
                float2 o0 = {fa[nt][0] + bb.x + r0.x, fa[nt][1] + bb.y + r0.y};
                *(float2*)(out + ((size_t)prev * 8 + lr) * 64 + c) = o0;
            }
        }
        if (t >= NTILES) break;
        const size_t R = (size_t)t * 128;

        // ---- warp0: q = x0 @ Wq^T + bq for the 8 distinct m-rows (overlapped) ----
        if (wid == 0) {
            size_t r1i = R + (size_t)(lr + 8) * 16;
            if (r1i > (size_t)(TOTROWS - 1)) r1i = (size_t)(TOTROWS - 1);  // rows 8..15 unused
            const float* p0 = x + (R + (size_t)lr * 16) * 64;
            const float* p1 = x + r1i * 64;
            uint32_t af[4][4];
#pragma unroll
            for (int kt = 0; kt < 4; kt++) {
                int k0 = kt * 16 + 2 * lc;
                float2 a00 = __ldg((const float2*)(p0 + k0));
                float2 a02 = __ldg((const float2*)(p0 + k0 + 8));
                float2 a10 = __ldg((const float2*)(p1 + k0));
                float2 a12 = __ldg((const float2*)(p1 + k0 + 8));
                af[kt][0] = pk(a00.x, a00.y); af[kt][2] = pk(a02.x, a02.y);
                af[kt][1] = pk(a10.x, a10.y); af[kt][3] = pk(a12.x, a12.y);
            }
            float qa[8][4];
#pragma unroll
            for (int nt = 0; nt < 8; nt++)
#pragma unroll
                for (int j = 0; j < 4; j++) qa[nt][j] = 0.0f;
            gemm64(qa, af, wfb + 0 * 2048, lane);                 // Wq
#pragma unroll
            for (int nt = 0; nt < 8; nt++) {
                int c = nt * 8 + 2 * lc;
                float2 bb = *(const float2*)(smf + OFF_BIAS + 5 * 64 + c);
                *(float2*)(smf + OFF_Q + lr * 68 + c) = make_float2(qa[nt][0] + bb.x, qa[nt][1] + bb.y);
            }
        }

        // ---- stage X (own rows) coalesced into OP as bf16x2 ----
        {
            const int r  = tid >> 1;
            const int hh = tid & 1;
            const float4* gx = (const float4*)(x + (R + r) * 64 + hh * 32);
            uint32_t* dst = smu + OFF_OP + r * 36 + hh * 16;
#pragma unroll
            for (int i = 0; i < 4; i++) {
                float4 v0 = __ldg(gx + 2 * i);
                float4 v1 = __ldg(gx + 2 * i + 1);
                uint4 u;
                u.x = pk(v0.x, v0.y); u.y = pk(v0.z, v0.w);
                u.z = pk(v1.x, v1.y); u.w = pk(v1.z, v1.w);
                *(uint4*)(dst + i * 4) = u;
            }
        }
        __syncwarp();

        // ---- HP (pos-MLP hidden) directly into A-fragment registers ----
        uint32_t hpaf[4][4];
        {
            const float* zb = xyz + (R + (size_t)wid * 16) * 3;
            float bx = __ldg(zb + 0), by = __ldg(zb + 1), bz = __ldg(zb + 2);
            float r00 = __ldg(zb + lr * 3 + 0) - bx;
            float r01 = __ldg(zb + lr * 3 + 1) - by;
            float r02 = __ldg(zb + lr * 3 + 2) - bz;
            float r10 = __ldg(zb + (lr + 8) * 3 + 0) - bx;
            float r11 = __ldg(zb + (lr + 8) * 3 + 1) - by;
            float r12 = __ldg(zb + (lr + 8) * 3 + 2) - bz;
#pragma unroll
            for (int kt = 0; kt < 4; kt++)
#pragma unroll
                for (int s = 0; s < 2; s++) {
                    int d = kt * 16 + 2 * lc + 8 * s;
                    float4 wA = *(const float4*)(smf + OFF_WP1 + 4 * d);
                    float4 wB = *(const float4*)(smf + OFF_WP1 + 4 * (d + 1));
                    float hA0 = wA.w, hB0 = wB.w, hA1 = wA.w, hB1 = wB.w;
                    hA0 = fmaf(r00, wA.x, hA0); hA0 = fmaf(r01, wA.y, hA0); hA0 = fmaf(r02, wA.z, hA0);
                    hB0 = fmaf(r00, wB.x, hB0); hB0 = fmaf(r01, wB.y, hB0); hB0 = fmaf(r02, wB.z, hB0);
                    hA1 = fmaf(r10, wA.x, hA1); hA1 = fmaf(r11, wA.y, hA1); hA1 = fmaf(r12, wA.z, hA1);
                    hB1 = fmaf(r10, wB.x, hB1); hB1 = fmaf(r11, wB.y, hB1); hB1 = fmaf(r12, wB.z, hB1);
                    hpaf[kt][2 * s + 0] = pk(fmaxf(hA0, 0.0f), fmaxf(hB0, 0.0f));   // row lr
                    hpaf[kt][2 * s + 1] = pk(fmaxf(hA1, 0.0f), fmaxf(hB1, 0.0f));   // row lr+8
                }
        }

        // ---- fused stage-1 GEMMs ----
        float lacc[8][4], vacc[8][4];
#pragma unroll
        for (int nt = 0; nt < 8; nt++)
#pragma unroll
            for (int j = 0; j < 4; j++) { lacc[nt][j] = 0.0f; vacc[nt][j] = 0.0f; }
        {
            uint32_t xaf[4][4];
            load_af(xaf, smu + OFF_OP + rb * 36, lr, lc);
            gemm64_dual(lacc, vacc, xaf, wfb + 1 * 2048, wfb + 2 * 2048, lane);   // -Wk, Wv
        }
        gemm64_shared(lacc, vacc, hpaf, wfb + 3 * 2048, lane);                    // Wp2 -> both
        __syncthreads();   // q ready for everyone

        // ---- h epilogue: h = lacc + bh + q[m] -> bf16 -> OP in place ----
#pragma unroll
        for (int nt = 0; nt < 8; nt++) {
            int c = nt * 8 + 2 * lc;
            float2 qv = *(const float2*)(smf + OFF_Q + wid * 68 + c);
            float2 bh = *(const float2*)(smf + OFF_BIAS + c);
            smu[OFF_OP + (rb + lr) * 36 + nt * 4 + lc]     = pk(lacc[nt][0] + bh.x + qv.x,
                                                                lacc[nt][1] + bh.y + qv.y);
            smu[OFF_OP + (rb + lr + 8) * 36 + nt * 4 + lc] = pk(lacc[nt][2] + bh.x + qv.x,
                                                                lacc[nt][3] + bh.y + qv.y);
        }
        __syncwarp();

        // ---- a1 = relu(h @ Wa1^T + ba1) -> OP in place ----
        float aacc[8][4];
#pragma unroll
        for (int nt = 0; nt < 8; nt++)
#pragma unroll
            for (int j = 0; j < 4; j++) aacc[nt][j] = 0.0f;
        {
            uint32_t af[4][4];
            load_af(af, smu + OFF_OP + rb * 36, lr, lc);
            gemm64(aacc, af, wfb + 4 * 2048, lane);                               // Wa1
        }
#pragma unroll
        for (int nt = 0; nt < 8; nt++) {
            int c = nt * 8 + 2 * lc;
            float2 bb = *(const float2*)(smf + OFF_BIAS + 2 * 64 + c);
            smu[OFF_OP + (rb + lr) * 36 + nt * 4 + lc]     = pk(fmaxf(aacc[nt][0] + bb.x, 0.0f),
                                                                fmaxf(aacc[nt][1] + bb.y, 0.0f));
            smu[OFF_OP + (rb + lr + 8) * 36 + nt * 4 + lc] = pk(fmaxf(aacc[nt][2] + bb.x, 0.0f),
                                                                fmaxf(aacc[nt][3] + bb.y, 0.0f));
        }
        __syncwarp();

        // ---- logits = a1 @ Wa2^T ----
        float gacc[8][4];
#pragma unroll
        for (int nt = 0; nt < 8; nt++)
#pragma unroll
            for (int j = 0; j < 4; j++) gacc[nt][j] = 0.0f;
        {
            uint32_t af[4][4];
            load_af(af, smu + OFF_OP + rb * 36, lr, lc);
            gemm64(gacc, af, wfb + 5 * 2048, lane);                               // Wa2
        }

        // ---- softmax over 16 neighbors + weighted sum -> RES (bf16) ----
#pragma unroll
        for (int nt = 0; nt < 8; nt++) {
            int c = nt * 8 + 2 * lc;
            float2 ba = *(const float2*)(smf + OFF_BIAS + 3 * 64 + c);
            float2 bv = *(const float2*)(smf + OFF_BIAS + 1 * 64 + c);
            float rr[2];
#pragma unroll
            for (int jc = 0; jc < 2; jc++) {
                float bav = jc ? ba.y : ba.x;
                float bvv = jc ? bv.y : bv.x;
                float l0 = (gacc[nt][jc]     + bav) * 0.125f;   // n = lr
                float l2 = (gacc[nt][jc + 2] + bav) * 0.125f;   // n = lr+8
                float mx = fmaxf(l0, l2);
                mx = fmaxf(mx, __shfl_xor_sync(0xffffffffu, mx, 4));
                mx = fmaxf(mx, __shfl_xor_sync(0xffffffffu, mx, 8));
                mx = fmaxf(mx, __shfl_xor_sync(0xffffffffu, mx, 16));
                float e0 = __expf(l0 - mx), e2 = __expf(l2 - mx);
                float v0 = vacc[nt][jc] + bvv, v2 = vacc[nt][jc + 2] + bvv;
                float s = e0 + e2;
                float w = e0 * v0 + e2 * v2;
                s += __shfl_xor_sync(0xffffffffu, s, 4);  w += __shfl_xor_sync(0xffffffffu, w, 4);
                s += __shfl_xor_sync(0xffffffffu, s, 8);  w += __shfl_xor_sync(0xffffffffu, w, 8);
                s += __shfl_xor_sync(0xffffffffu, s, 16); w += __shfl_xor_sync(0xffffffffu, w, 16);
                rr[jc] = w / s;
            }
            if (lr == 0)
                smu[OFF_RES + wid * 36 + nt * 4 + lc] = pk(rr[0], rr[1]);
        }
        prev = t;
    }
}

extern "C" void kernel_launch(void* const* d_in, const int* in_sizes, int n_in,
                              void* d_out, int out_size)
{
    const float* x   = (const float*)d_in[0];
    const float* xyz = (const float*)d_in[1];
    const float* Wq  = (const float*)d_in[2];
    const float* bq  = (const float*)d_in[3];
    const float* Wk  = (const float*)d_in[4];
    const float* bk  = (const float*)d_in[5];
    const float* Wv  = (const float*)d_in[6];
    const float* bv  = (const float*)d_in[7];
    const float* Wp1 = (const float*)d_in[8];
    const float* bp1 = (const float*)d_in[9];
    const float* Wp2 = (const float*)d_in[10];
    const float* bp2 = (const float*)d_in[11];
    const float* Wa1 = (const float*)d_in[12];
    const float* ba1 = (const float*)d_in[13];
    const float* Wa2 = (const float*)d_in[14];
    const float* ba2 = (const float*)d_in[15];
    const float* W2  = (const float*)d_in[16];
    const float* b2  = (const float*)d_in[17];

    cudaFuncSetAttribute(la_mma, cudaFuncAttributeMaxDynamicSharedMemorySize, SMEM_BYTES);

    la_mma<<<GRID, THREADS, SMEM_BYTES>>>(x, xyz, Wq, bq, Wk, bk, Wv, bv,
                                          Wp1, bp1, Wp2, bp2, Wa1, ba1,
                                          Wa2, ba2, W2, b2, (float*)d_out);
}